// round 6
// baseline (speedup 1.0000x reference)
#include <cuda_runtime.h>
#include <cuda_fp16.h>
#include <math.h>

#define L_SEQ 2048
#define H_DIM 2048
#define G3H   6144
#define NCTA  128
#define TPB   512     // 16 warps; warp w owns j = cta*16 + w
#define FLAG_STRIDE 8 // words between per-CTA flags (32B spacing)

// -------- device-global scratch (no allocations allowed) --------
__device__ float g_gi[(size_t)L_SEQ * G3H];         // 48 MB: x@W_ih^T + b_ih (+ b_hh for r,z)
__device__ __align__(16) __half g_h16[2][H_DIM];    // double-buffered fp16 h broadcast
__device__ unsigned int g_hflag[NCTA * FLAG_STRIDE];// per-CTA progress flags (step count)

__device__ __forceinline__ __half2 u2h2(unsigned u) {
    return *reinterpret_cast<__half2*>(&u);
}

// ============================================================
// Kernel A: g_gi[t][r] = x[t]·w_ih[r] + b_ih[r] + (r<2H ? b_hh[r] : 0)
// (n-gate's b_hh must stay inside the reset product — added in kernel B)
// Block (0,0) also zeroes the per-CTA flags for this launch.
// ============================================================
#define BM 64
#define BN 64
#define BK 16

__global__ void __launch_bounds__(256) gemm_gi_kernel(const float* __restrict__ X,
                                                      const float* __restrict__ W,
                                                      const float* __restrict__ b_ih,
                                                      const float* __restrict__ b_hh) {
    if (blockIdx.x == 0 && blockIdx.y == 0) {
#pragma unroll
        for (int i = 0; i < 4; i++)
            g_hflag[threadIdx.x + i * 256] = 0u;    // 1024 words
    }

    __shared__ float As[BK][BM + 4];
    __shared__ float Bs[BK][BN + 4];
    const int K = H_DIM;
    const int bm = blockIdx.y * BM;
    const int bn = blockIdx.x * BN;
    const int tid = threadIdx.x;
    const int tm = tid >> 4;
    const int tn = tid & 15;

    unsigned long long c[2][4];
#pragma unroll
    for (int i = 0; i < 2; i++)
#pragma unroll
        for (int j = 0; j < 4; j++) c[i][j] = 0ull;

    const int lrow = tid >> 2;
    const int lk   = (tid & 3) << 2;

    for (int k0 = 0; k0 < K; k0 += BK) {
        float4 av = *reinterpret_cast<const float4*>(&X[(size_t)(bm + lrow) * K + k0 + lk]);
        float4 bv = *reinterpret_cast<const float4*>(&W[(size_t)(bn + lrow) * K + k0 + lk]);
        As[lk + 0][lrow] = av.x; As[lk + 1][lrow] = av.y;
        As[lk + 2][lrow] = av.z; As[lk + 3][lrow] = av.w;
        Bs[lk + 0][lrow] = bv.x; Bs[lk + 1][lrow] = bv.y;
        Bs[lk + 2][lrow] = bv.z; Bs[lk + 3][lrow] = bv.w;
        __syncthreads();
#pragma unroll
        for (int k = 0; k < BK; k++) {
            float4 a = *reinterpret_cast<const float4*>(&As[k][tm << 2]);
            float4 b = *reinterpret_cast<const float4*>(&Bs[k][tn << 2]);
            unsigned long long a01, a23;
            asm("mov.b64 %0, {%1, %2};" : "=l"(a01) : "r"(__float_as_uint(a.x)), "r"(__float_as_uint(a.y)));
            asm("mov.b64 %0, {%1, %2};" : "=l"(a23) : "r"(__float_as_uint(a.z)), "r"(__float_as_uint(a.w)));
            float bj[4] = {b.x, b.y, b.z, b.w};
#pragma unroll
            for (int j = 0; j < 4; j++) {
                unsigned long long bb;
                asm("mov.b64 %0, {%1, %1};" : "=l"(bb) : "r"(__float_as_uint(bj[j])));
                asm("fma.rn.f32x2 %0, %1, %2, %0;" : "+l"(c[0][j]) : "l"(a01), "l"(bb));
                asm("fma.rn.f32x2 %0, %1, %2, %0;" : "+l"(c[1][j]) : "l"(a23), "l"(bb));
            }
        }
        __syncthreads();
    }
#pragma unroll
    for (int i2 = 0; i2 < 2; i2++) {
#pragma unroll
        for (int j = 0; j < 4; j++) {
            unsigned lo, hi;
            asm("mov.b64 {%0, %1}, %2;" : "=r"(lo), "=r"(hi) : "l"(c[i2][j]));
            int col  = bn + (tn << 2) + j;
            float bs = b_ih[col] + ((col < 2 * H_DIM) ? b_hh[col] : 0.0f);
            int row0 = bm + (tm << 2) + i2 * 2;
            g_gi[(size_t)row0 * G3H + col]       = __uint_as_float(lo) + bs;
            g_gi[(size_t)(row0 + 1) * G3H + col] = __uint_as_float(hi) + bs;
        }
    }
}

// ============================================================
// Kernel B: persistent GRU recurrence — per-CTA flags, fused fetch.
// 128 CTAs x 512 threads (16 warps). Warp w owns j = cta*16 + w:
// 3 gate rows, weights in 96 half2 registers per lane.
// Per step:
//   consumers (tid<256): poll flag[tid>>1] >= t (ld.acquire.gpu),
//     then __ldcg own uint4 of h_t -> SMEM; bar;
//   matvec (regs x SMEM h); butterfly reduce; lane0 gates ->
//     store h_{t+1} (fp16) + out; bar; tid0 st.release flag = t+1.
// ============================================================
__global__ void __launch_bounds__(TPB, 1) gru_kernel(const float* __restrict__ w_hh,
                                                     const float* __restrict__ b_hh,
                                                     float* __restrict__ out,
                                                     int out_elems) {
    __shared__ uint4 sH[H_DIM / 8];     // 2048 halfs = 4KB

    const int tid  = threadIdx.x;
    const int warp = tid >> 5;
    const int lane = tid & 31;
    const int j    = blockIdx.x * 16 + warp;

    // ---- prologue: 3 rows of W_hh into 96 half2 registers ----
    __half2 w[3][8][4];
#pragma unroll
    for (int g = 0; g < 3; g++) {
        const float* wr = w_hh + (size_t)(g * H_DIM + j) * H_DIM;
#pragma unroll
        for (int i = 0; i < 8; i++) {
            int k = i * 256 + lane * 8;
            float4 a = *reinterpret_cast<const float4*>(wr + k);
            float4 b = *reinterpret_cast<const float4*>(wr + k + 4);
            w[g][i][0] = __floats2half2_rn(a.x, a.y);
            w[g][i][1] = __floats2half2_rn(a.z, a.w);
            w[g][i][2] = __floats2half2_rn(b.x, b.y);
            w[g][i][3] = __floats2half2_rn(b.z, b.w);
        }
    }

    float h_own = 0.0f;
    const float bhn = (lane == 0) ? b_hh[2 * H_DIM + j] : 0.0f;  // n-gate recurrent bias
    const float* gi_ptr  = g_gi + j;
    float*       out_ptr = out + j;
    // consumer thread tid<256 polls the flag of the CTA owning halfs [8*tid, 8*tid+8)
    const unsigned int* my_flag = &g_hflag[(tid >> 1) * FLAG_STRIDE];

    for (int t = 0; t < L_SEQ; t++) {
        // ---- gi prefetch (lands while polling) ----
        float ir = 0.f, iz = 0.f, inn = 0.f;
        if (lane == 0) {
            ir  = gi_ptr[0];
            iz  = gi_ptr[H_DIM];
            inn = gi_ptr[2 * H_DIM];
        }

        if (t > 0) {
            // ---- fused wait + fetch: poll producer's flag, then grab its h ----
            if (tid < H_DIM / 8) {
                const unsigned tg = (unsigned)t;
                unsigned v;
                do {
                    asm volatile("ld.acquire.gpu.global.u32 %0, [%1];"
                                 : "=r"(v) : "l"(my_flag) : "memory");
                } while (v < tg);
                sH[tid] = __ldcg(reinterpret_cast<const uint4*>(&g_h16[t & 1][0]) + tid);
            }
        }
        __syncthreads();

        // ---- matvec: 3 rows, weights in regs, h from SMEM ----
        float acc[3] = {0.f, 0.f, 0.f};
        if (t > 0) {
#pragma unroll
            for (int ii = 0; ii < 4; ii++) {
                uint4 hv0 = sH[(2 * ii) * 32 + lane];
                uint4 hv1 = sH[(2 * ii + 1) * 32 + lane];
                __half2 a0 = u2h2(hv0.x), a1 = u2h2(hv0.y), a2 = u2h2(hv0.z), a3 = u2h2(hv0.w);
                __half2 b0 = u2h2(hv1.x), b1 = u2h2(hv1.y), b2 = u2h2(hv1.z), b3 = u2h2(hv1.w);
#pragma unroll
                for (int g = 0; g < 3; g++) {
                    __half2 s = __hmul2(w[g][2 * ii][0], a0);
                    s = __hfma2(w[g][2 * ii][1], a1, s);
                    s = __hfma2(w[g][2 * ii][2], a2, s);
                    s = __hfma2(w[g][2 * ii][3], a3, s);
                    s = __hfma2(w[g][2 * ii + 1][0], b0, s);
                    s = __hfma2(w[g][2 * ii + 1][1], b1, s);
                    s = __hfma2(w[g][2 * ii + 1][2], b2, s);
                    s = __hfma2(w[g][2 * ii + 1][3], b3, s);
                    float2 f = __half22float2(s);     // flush to fp32 every 16 MACs
                    acc[g] += f.x + f.y;
                }
            }
        }

        // ---- butterfly reduce over 32 lanes ----
#pragma unroll
        for (int off = 16; off; off >>= 1) {
#pragma unroll
            for (int g = 0; g < 3; g++)
                acc[g] += __shfl_xor_sync(0xffffffffu, acc[g], off);
        }

        // ---- gates + state update (lane 0) ----
        if (lane == 0) {
            float rg = 1.0f / (1.0f + expf(-(ir + acc[0])));
            float zg = 1.0f / (1.0f + expf(-(iz + acc[1])));
            float ng = tanhf(inn + rg * (acc[2] + bhn));
            float hn = (1.0f - zg) * ng + zg * h_own;
            h_own = hn;
            out_ptr[0] = hn;
            g_h16[(t + 1) & 1][j] = __float2half(hn);
            if (t == L_SEQ - 1) {
                size_t base = (size_t)L_SEQ * H_DIM;
                if ((long long)(base + j) < out_elems)          out[base + j] = hn;
                if ((long long)(base + H_DIM + j) < out_elems)  out[base + H_DIM + j] = hn;
            }
        }
        __syncthreads();   // all h stores done; also guards sH reuse

        // ---- publish: release store of this CTA's step flag ----
        if (tid == 0) {
            asm volatile("st.release.gpu.global.u32 [%0], %1;"
                         :: "l"(&g_hflag[blockIdx.x * FLAG_STRIDE]), "r"((unsigned)(t + 1))
                         : "memory");
        }

        gi_ptr  += G3H;
        out_ptr += H_DIM;
    }
}

// ============================================================
extern "C" void kernel_launch(void* const* d_in, const int* in_sizes, int n_in,
                              void* d_out, int out_size) {
    const float* x    = (const float*)d_in[0];
    const float* w_ih = (const float*)d_in[1];
    const float* w_hh = (const float*)d_in[2];
    const float* b_ih = (const float*)d_in[3];
    const float* b_hh = (const float*)d_in[4];
    float* out = (float*)d_out;

    gemm_gi_kernel<<<dim3(G3H / BN, L_SEQ / BM), 256>>>(x, w_ih, b_ih, b_hh);
    gru_kernel<<<NCTA, TPB>>>(w_hh, b_hh, out, out_size);
}